// round 13
// baseline (speedup 1.0000x reference)
#include <cuda_runtime.h>
#include <cstdint>

#define B_  2
#define N_  1024
#define M_  1024
#define H_  128
#define G_  128
#define SCALE_ (1.0f / 6.964404506368992f)  // 1 / 128^0.4

__device__ float g_es[B_ * M_];       // exp(scaled logits)
__device__ float g_psum[G_];          // per-block partial exp sums (64 per batch)
__device__ unsigned g_count;          // monotonic ticket barrier (zero-init)

// dyn smem layout (bytes):
//   [0,8)           mbar
//   [128, 65664)    W tile (64 KB)
//   [65664, 82048)  part[1024] float4 partial colsums (16 KB)
//   [82048, 82560)  wcol[128]
//   [82560, 82624)  sh_e[16]
//   [82624, 82688)  sh_val[16]
//   [82688, 82692)  sh_inv
#define SMEM_BYTES 82752

__device__ __forceinline__ uint32_t smem_u32(const void* p) {
    uint32_t a;
    asm("{ .reg .u64 t; cvta.to.shared.u64 t, %1; cvt.u32.u64 %0, t; }"
        : "=r"(a) : "l"(p));
    return a;
}

__global__ __launch_bounds__(1024) void k_fused(const float* __restrict__ keys,
                                                const float* __restrict__ values,
                                                const float* __restrict__ W,
                                                float* __restrict__ out) {
    extern __shared__ char smem[];
    float*  shW    = reinterpret_cast<float*>(smem + 128);
    float4* part   = reinterpret_cast<float4*>(smem + 65664);   // 1024 float4
    float*  wcol   = reinterpret_cast<float*>(smem + 82048);
    float*  sh_e   = reinterpret_cast<float*>(smem + 82560);
    float*  sh_val = reinterpret_cast<float*>(smem + 82624);
    float*  sh_inv = reinterpret_cast<float*>(smem + 82688);

    const int tid  = threadIdx.x;
    const int lane = tid & 31;
    const int warp = tid >> 5;
    const int blk  = blockIdx.x;
    const uint32_t mbar = smem_u32(smem);

    // ---------------- Phase A: init mbar, sync, THEN issue bulk W copy -----
    if (tid == 0) {
        asm volatile("mbarrier.init.shared.b64 [%0], 1;" :: "r"(mbar) : "memory");
    }
    __syncthreads();
    if (tid == 0) {
        asm volatile("mbarrier.arrive.expect_tx.shared.b64 _, [%0], %1;"
                     :: "r"(mbar), "r"(65536u) : "memory");
        asm volatile(
            "cp.async.bulk.shared::cta.global.mbarrier::complete_tx::bytes "
            "[%0], [%1], %2, [%3];"
            :: "r"(smem_u32(shW)), "l"(W), "r"(65536u), "r"(mbar) : "memory");
    }

    // keys rows (16 rows, one warp each) AND values (warp 16) -> overlapped
    float4 k4 = make_float4(0.f, 0.f, 0.f, 0.f);
    if (warp < 16) {
        k4 = reinterpret_cast<const float4*>(keys)[(blk * 16 + warp) * 32 + lane];
    } else if (warp == 16 && lane < 16) {
        sh_val[lane] = values[blk * 16 + lane];   // cold DRAM read, pre-barrier
    }

    // ---------------- wait for W ------------------------------------------
    {
        uint32_t done;
        asm volatile(
            "{\n\t.reg .pred p;\n\t"
            "mbarrier.try_wait.parity.acquire.cta.shared::cta.b64 p, [%1], 0;\n\t"
            "selp.b32 %0, 1, 0, p;\n\t}"
            : "=r"(done) : "r"(mbar) : "memory");
        while (!done) {
            asm volatile(
                "{\n\t.reg .pred p;\n\t"
                "mbarrier.try_wait.parity.acquire.cta.shared::cta.b64 p, [%1], 0, 0x989680;\n\t"
                "selp.b32 %0, 1, 0, p;\n\t}"
                : "=r"(done) : "r"(mbar) : "memory");
        }
    }
    __syncthreads();

    // ---------------- Phase B: colsum(W) in smem ---------------------------
    {
        const int c4 = tid & 31;              // float4 column
        const int g  = tid >> 5;              // 32 groups x 4 rows
        const float4* W4 = reinterpret_cast<const float4*>(shW);
        float4 a = W4[(g * 4 + 0) * 32 + c4];
        float4 b1 = W4[(g * 4 + 1) * 32 + c4];
        float4 c1 = W4[(g * 4 + 2) * 32 + c4];
        float4 d1 = W4[(g * 4 + 3) * 32 + c4];
        part[g * 32 + c4] = make_float4((a.x + b1.x) + (c1.x + d1.x),
                                        (a.y + b1.y) + (c1.y + d1.y),
                                        (a.z + b1.z) + (c1.z + d1.z),
                                        (a.w + b1.w) + (c1.w + d1.w));
    }
    __syncthreads();
    if (tid < 32) {
        float4 s = make_float4(0.f, 0.f, 0.f, 0.f);
        #pragma unroll
        for (int g = 0; g < 32; ++g) {
            float4 p = part[g * 32 + tid];
            s.x += p.x; s.y += p.y; s.z += p.z; s.w += p.w;
        }
        reinterpret_cast<float4*>(wcol)[tid] = s;
    }
    __syncthreads();

    // ---------------- dots + exp + block partial sum -----------------------
    if (warp < 16) {
        const float4 w4 = reinterpret_cast<const float4*>(wcol)[lane];
        float acc = k4.x * w4.x + k4.y * w4.y + k4.z * w4.z + k4.w * w4.w;
        #pragma unroll
        for (int o = 16; o > 0; o >>= 1) acc += __shfl_xor_sync(0xffffffffu, acc, o);
        if (lane == 0) {
            const float e = __expf(SCALE_ * acc);
            __stcg(&g_es[blk * 16 + warp], e);
            sh_e[warp] = e;
        }
    }
    __syncthreads();
    if (warp == 0) {
        float v = (lane < 16) ? sh_e[lane] : 0.f;
        #pragma unroll
        for (int o = 16; o > 0; o >>= 1) v += __shfl_xor_sync(0xffffffffu, v, o);
        if (lane == 0) __stcg(&g_psum[blk], v);   // blocks 0..63 batch0, 64..127 batch1
    }

    // ---------------- grid barrier (monotonic ticket) ----------------------
    __syncthreads();
    if (tid == 0) {
        __threadfence();
        const unsigned ticket = atomicAdd(&g_count, 1u);
        const unsigned target = (ticket / G_ + 1u) * G_;
        while (*((volatile unsigned*)&g_count) < target) { }
        __threadfence();
    }
    __syncthreads();

    // ---------------- Phase C: denom --------------------------------------
    const int b = blk >> 6;
    // issue the softmax-row float4 read early (L2-hot)
    const int col = tid & 255;                 // float4 column within row
    const int r0  = tid >> 8;                  // 0..3 row-quarter
    const float4 e4 = __ldcg(
        reinterpret_cast<const float4*>(g_es) + (b << 8) + col);

    if (warp == 0) {
        float p = __ldcg(&g_psum[b * 64 + lane]) + __ldcg(&g_psum[b * 64 + 32 + lane]);
        #pragma unroll
        for (int o = 16; o > 0; o >>= 1) p += __shfl_xor_sync(0xffffffffu, p, o);
        if (lane == 0) *sh_inv = 1.0f / p;
    }
    __syncthreads();
    const float inv = *sh_inv;
    const float4 s4 = make_float4(e4.x * inv, e4.y * inv, e4.z * inv, e4.w * inv);

    // ---------------- Phase D: write 16 output rows (STG.128) --------------
    float4* o4 = reinterpret_cast<float4*>(out);
    #pragma unroll
    for (int i = 0; i < 4; ++i) {
        const int rl = i * 4 + r0;             // local row 0..15
        const float v = sh_val[rl];
        o4[(size_t)(blk * 16 + rl) * 256 + col] =
            make_float4(s4.x * v, s4.y * v, s4.z * v, s4.w * v);
    }
}

extern "C" void kernel_launch(void* const* d_in, const int* in_sizes, int n_in,
                              void* d_out, int out_size) {
    // metadata order: queries, keys, values, W, b (queries & bias cancel in softmax)
    const float* keys   = (const float*)d_in[1];
    const float* values = (const float*)d_in[2];
    const float* W      = (const float*)d_in[3];
    float* out = (float*)d_out;

    cudaFuncSetAttribute(k_fused, cudaFuncAttributeMaxDynamicSharedMemorySize,
                         SMEM_BYTES);
    k_fused<<<G_, 1024, SMEM_BYTES>>>(keys, values, W, out);
}

// round 14
// speedup vs baseline: 1.0058x; 1.0058x over previous
#include <cuda_runtime.h>
#include <cstdint>

#define B_  2
#define N_  1024
#define M_  1024
#define H_  128
#define G_  64           // grid size (single wave), 32 rows per block
#define SCALE_ (1.0f / 6.964404506368992f)  // 1 / 128^0.4

__device__ float g_es[B_ * M_];       // exp(scaled logits)
__device__ float g_psum[G_];          // per-block partial exp sums (32 per batch)
__device__ unsigned g_count;          // monotonic ticket barrier (zero-init)

// dyn smem layout (bytes):
//   [0,8)           mbar
//   [128, 65664)    W tile (64 KB)
//   [65664, 82048)  part[1024] float4 partial colsums (16 KB)
//   [82048, 82560)  wcol[128]
//   [82560, 82688)  sh_e[32]
//   [82688, 82816)  sh_val[32]
#define SMEM_BYTES 82944

__device__ __forceinline__ uint32_t smem_u32(const void* p) {
    uint32_t a;
    asm("{ .reg .u64 t; cvta.to.shared.u64 t, %1; cvt.u32.u64 %0, t; }"
        : "=r"(a) : "l"(p));
    return a;
}

__global__ __launch_bounds__(1024) void k_fused(const float* __restrict__ keys,
                                                const float* __restrict__ values,
                                                const float* __restrict__ W,
                                                float* __restrict__ out) {
    extern __shared__ char smem[];
    float*  shW    = reinterpret_cast<float*>(smem + 128);
    float4* part   = reinterpret_cast<float4*>(smem + 65664);   // 1024 float4
    float*  wcol   = reinterpret_cast<float*>(smem + 82048);
    float*  sh_e   = reinterpret_cast<float*>(smem + 82560);
    float*  sh_val = reinterpret_cast<float*>(smem + 82688);

    const int tid  = threadIdx.x;
    const int lane = tid & 31;
    const int warp = tid >> 5;                 // 0..31
    const int blk  = blockIdx.x;               // 0..63
    const uint32_t mbar = smem_u32(smem);

    // ---------------- Phase A: init mbar, sync, issue bulk W copy ----------
    if (tid == 0) {
        asm volatile("mbarrier.init.shared.b64 [%0], 1;" :: "r"(mbar) : "memory");
    }
    __syncthreads();
    if (tid == 0) {
        asm volatile("mbarrier.arrive.expect_tx.shared.b64 _, [%0], %1;"
                     :: "r"(mbar), "r"(65536u) : "memory");
        asm volatile(
            "cp.async.bulk.shared::cta.global.mbarrier::complete_tx::bytes "
            "[%0], [%1], %2, [%3];"
            :: "r"(smem_u32(shW)), "l"(W), "r"(65536u), "r"(mbar) : "memory");
    }

    // each warp owns key row blk*32+warp; lane 0 also fetches its value
    const int row = blk * 32 + warp;
    const float4 k4 = reinterpret_cast<const float4*>(keys)[row * 32 + lane];
    if (lane == 0) sh_val[warp] = values[row];

    // ---------------- wait for W ------------------------------------------
    {
        uint32_t done;
        asm volatile(
            "{\n\t.reg .pred p;\n\t"
            "mbarrier.try_wait.parity.acquire.cta.shared::cta.b64 p, [%1], 0;\n\t"
            "selp.b32 %0, 1, 0, p;\n\t}"
            : "=r"(done) : "r"(mbar) : "memory");
        while (!done) {
            asm volatile(
                "{\n\t.reg .pred p;\n\t"
                "mbarrier.try_wait.parity.acquire.cta.shared::cta.b64 p, [%1], 0, 0x989680;\n\t"
                "selp.b32 %0, 1, 0, p;\n\t}"
                : "=r"(done) : "r"(mbar) : "memory");
        }
    }
    __syncthreads();

    // ---------------- Phase B: colsum(W) in smem ---------------------------
    {
        const int c4 = tid & 31;               // float4 column
        const int g  = tid >> 5;               // 32 groups x 4 rows
        const float4* W4 = reinterpret_cast<const float4*>(shW);
        float4 a  = W4[(g * 4 + 0) * 32 + c4];
        float4 b1 = W4[(g * 4 + 1) * 32 + c4];
        float4 c1 = W4[(g * 4 + 2) * 32 + c4];
        float4 d1 = W4[(g * 4 + 3) * 32 + c4];
        part[g * 32 + c4] = make_float4((a.x + b1.x) + (c1.x + d1.x),
                                        (a.y + b1.y) + (c1.y + d1.y),
                                        (a.z + b1.z) + (c1.z + d1.z),
                                        (a.w + b1.w) + (c1.w + d1.w));
    }
    __syncthreads();
    if (tid < 32) {
        float4 s = make_float4(0.f, 0.f, 0.f, 0.f);
        #pragma unroll
        for (int g = 0; g < 32; ++g) {
            float4 p = part[g * 32 + tid];
            s.x += p.x; s.y += p.y; s.z += p.z; s.w += p.w;
        }
        reinterpret_cast<float4*>(wcol)[tid] = s;
    }
    __syncthreads();

    // ---------------- dots + exp + block partial sum -----------------------
    {
        const float4 w4 = reinterpret_cast<const float4*>(wcol)[lane];
        float acc = k4.x * w4.x + k4.y * w4.y + k4.z * w4.z + k4.w * w4.w;
        #pragma unroll
        for (int o = 16; o > 0; o >>= 1) acc += __shfl_xor_sync(0xffffffffu, acc, o);
        if (lane == 0) {
            const float e = __expf(SCALE_ * acc);
            __stcg(&g_es[row], e);
            sh_e[warp] = e;
        }
    }
    __syncthreads();
    if (warp == 0) {
        float v = sh_e[lane];
        #pragma unroll
        for (int o = 16; o > 0; o >>= 1) v += __shfl_xor_sync(0xffffffffu, v, o);
        if (lane == 0) __stcg(&g_psum[blk], v);  // blocks 0..31 batch0, 32..63 batch1
    }

    // ---------------- grid barrier (monotonic ticket, G=64) ----------------
    __syncthreads();
    if (tid == 0) {
        __threadfence();
        const unsigned ticket = atomicAdd(&g_count, 1u);
        const unsigned target = (ticket / G_ + 1u) * G_;
        while (*((volatile unsigned*)&g_count) < target) { }
        __threadfence();
    }
    __syncthreads();

    // ---------------- Phase C: denom (per-warp, no smem/sync) --------------
    const int b = blk >> 5;                    // 32 blocks per batch
    const int col = tid & 255;                 // float4 column within row
    const int q   = tid >> 8;                  // 0..3 row-quarter
    const float4 e4 = __ldcg(
        reinterpret_cast<const float4*>(g_es) + (b << 8) + col);

    float p = __ldcg(&g_psum[b * 32 + lane]);  // L2-hot broadcast
    #pragma unroll
    for (int o = 16; o > 0; o >>= 1) p += __shfl_xor_sync(0xffffffffu, p, o);
    const float inv = 1.0f / p;                // all lanes hold denom
    const float4 s4 = make_float4(e4.x * inv, e4.y * inv, e4.z * inv, e4.w * inv);

    // ---------------- Phase D: write 32 output rows (STG.128) --------------
    float4* o4 = reinterpret_cast<float4*>(out);
    #pragma unroll
    for (int i = 0; i < 8; ++i) {
        const int rl = i * 4 + q;              // local row 0..31
        const float v = sh_val[rl];
        o4[(size_t)(blk * 32 + rl) * 256 + col] =
            make_float4(s4.x * v, s4.y * v, s4.z * v, s4.w * v);
    }
}

extern "C" void kernel_launch(void* const* d_in, const int* in_sizes, int n_in,
                              void* d_out, int out_size) {
    // metadata order: queries, keys, values, W, b (queries & bias cancel in softmax)
    const float* keys   = (const float*)d_in[1];
    const float* values = (const float*)d_in[2];
    const float* W      = (const float*)d_in[3];
    float* out = (float*)d_out;

    cudaFuncSetAttribute(k_fused, cudaFuncAttributeMaxDynamicSharedMemorySize,
                         SMEM_BYTES);
    k_fused<<<G_, 1024, SMEM_BYTES>>>(keys, values, W, out);
}

// round 15
// speedup vs baseline: 1.0269x; 1.0209x over previous
#include <cuda_runtime.h>
#include <cstdint>

#define B_  2
#define N_  1024
#define M_  1024
#define H_  128
#define G_  128
#define SCALE_ (1.0f / 6.964404506368992f)  // 1 / 128^0.4

__device__ float g_es[B_ * M_];       // exp(scaled logits)
__device__ float g_psum[G_];          // per-block partial exp sums (64 per batch)
__device__ unsigned g_count;          // monotonic ticket barrier (zero-init)

// dyn smem layout (bytes):
//   [0,8)           mbar
//   [128, 65664)    W tile (64 KB)
//   [65664, 82048)  part[1024] float4 (16 KB)
//   [82048, 82560)  wcol[128]
//   [82560, 82624)  sh_e[16]
//   [82624, 82688)  sh_val[16]
#define SMEM_BYTES 82816

__device__ __forceinline__ uint32_t smem_u32(const void* p) {
    uint32_t a;
    asm("{ .reg .u64 t; cvta.to.shared.u64 t, %1; cvt.u32.u64 %0, t; }"
        : "=r"(a) : "l"(p));
    return a;
}

__global__ __launch_bounds__(1024) void k_fused(const float* __restrict__ keys,
                                                const float* __restrict__ values,
                                                const float* __restrict__ W,
                                                float* __restrict__ out) {
    extern __shared__ char smem[];
    float*  shW    = reinterpret_cast<float*>(smem + 128);
    float4* part   = reinterpret_cast<float4*>(smem + 65664);
    float*  wcol   = reinterpret_cast<float*>(smem + 82048);
    float*  sh_e   = reinterpret_cast<float*>(smem + 82560);
    float*  sh_val = reinterpret_cast<float*>(smem + 82624);

    const int tid  = threadIdx.x;
    const int lane = tid & 31;
    const int warp = tid >> 5;
    const int blk  = blockIdx.x;
    const uint32_t mbar = smem_u32(smem);

    // ---------------- Phase A: init mbar, sync, issue bulk W copy ----------
    if (tid == 0) {
        asm volatile("mbarrier.init.shared.b64 [%0], 1;" :: "r"(mbar) : "memory");
    }
    __syncthreads();
    if (tid == 0) {
        asm volatile("mbarrier.arrive.expect_tx.shared.b64 _, [%0], %1;"
                     :: "r"(mbar), "r"(65536u) : "memory");
        asm volatile(
            "cp.async.bulk.shared::cta.global.mbarrier::complete_tx::bytes "
            "[%0], [%1], %2, [%3];"
            :: "r"(smem_u32(shW)), "l"(W), "r"(65536u), "r"(mbar) : "memory");
    }

    // keys rows (16, one warp each); warp 16 prefetches values (cold DRAM)
    float4 k4 = make_float4(0.f, 0.f, 0.f, 0.f);
    if (warp < 16) {
        k4 = reinterpret_cast<const float4*>(keys)[(blk * 16 + warp) * 32 + lane];
    } else if (warp == 16 && lane < 16) {
        sh_val[lane] = values[blk * 16 + lane];
    }

    // ---------------- wait for W ------------------------------------------
    {
        uint32_t done;
        asm volatile(
            "{\n\t.reg .pred p;\n\t"
            "mbarrier.try_wait.parity.acquire.cta.shared::cta.b64 p, [%1], 0;\n\t"
            "selp.b32 %0, 1, 0, p;\n\t}"
            : "=r"(done) : "r"(mbar) : "memory");
        while (!done) {
            asm volatile(
                "{\n\t.reg .pred p;\n\t"
                "mbarrier.try_wait.parity.acquire.cta.shared::cta.b64 p, [%1], 0, 0x989680;\n\t"
                "selp.b32 %0, 1, 0, p;\n\t}"
                : "=r"(done) : "r"(mbar) : "memory");
        }
    }
    __syncthreads();

    // ---------------- Phase B: colsum(W) in smem ---------------------------
    {
        const int c4 = tid & 31;
        const int g  = tid >> 5;
        const float4* W4 = reinterpret_cast<const float4*>(shW);
        float4 a  = W4[(g * 4 + 0) * 32 + c4];
        float4 b1 = W4[(g * 4 + 1) * 32 + c4];
        float4 c1 = W4[(g * 4 + 2) * 32 + c4];
        float4 d1 = W4[(g * 4 + 3) * 32 + c4];
        part[g * 32 + c4] = make_float4((a.x + b1.x) + (c1.x + d1.x),
                                        (a.y + b1.y) + (c1.y + d1.y),
                                        (a.z + b1.z) + (c1.z + d1.z),
                                        (a.w + b1.w) + (c1.w + d1.w));
    }
    __syncthreads();
    if (tid < 32) {
        float4 s = make_float4(0.f, 0.f, 0.f, 0.f);
        #pragma unroll
        for (int g = 0; g < 32; ++g) {
            float4 p = part[g * 32 + tid];
            s.x += p.x; s.y += p.y; s.z += p.z; s.w += p.w;
        }
        reinterpret_cast<float4*>(wcol)[tid] = s;
    }
    __syncthreads();

    // ---------------- dots + exp + block partial sum -----------------------
    if (warp < 16) {
        const float4 w4 = reinterpret_cast<const float4*>(wcol)[lane];
        float acc = k4.x * w4.x + k4.y * w4.y + k4.z * w4.z + k4.w * w4.w;
        #pragma unroll
        for (int o = 16; o > 0; o >>= 1) acc += __shfl_xor_sync(0xffffffffu, acc, o);
        if (lane == 0) {
            const float e = __expf(SCALE_ * acc);
            __stcg(&g_es[blk * 16 + warp], e);
            sh_e[warp] = e;
        }
    }
    __syncthreads();
    if (warp == 0) {
        float v = (lane < 16) ? sh_e[lane] : 0.f;
        #pragma unroll
        for (int o = 16; o > 0; o >>= 1) v += __shfl_xor_sync(0xffffffffu, v, o);
        if (lane == 0) __stcg(&g_psum[blk], v);
    }

    // ---------------- grid barrier: release-arrive / acquire-poll ----------
    __syncthreads();   // makes all block writes visible to tid0 (cumulativity)
    if (tid == 0) {
        unsigned ticket;
        asm volatile("atom.add.release.gpu.u32 %0, [%1], %2;"
                     : "=r"(ticket) : "l"(&g_count), "r"(1u) : "memory");
        const unsigned target = (ticket / G_ + 1u) * G_;
        unsigned cur;
        do {
            asm volatile("ld.acquire.gpu.u32 %0, [%1];"
                         : "=r"(cur) : "l"(&g_count) : "memory");
        } while (cur < target);
    }
    __syncthreads();

    // ---------------- Phase C: denom per-warp (no smem, no sync) -----------
    const int b   = blk >> 6;
    const int col = tid & 255;
    const int q   = tid >> 8;
    const float4 e4 = __ldcg(
        reinterpret_cast<const float4*>(g_es) + (b << 8) + col);

    float p = __ldcg(&g_psum[b * 64 + lane]) + __ldcg(&g_psum[b * 64 + 32 + lane]);
    #pragma unroll
    for (int o = 16; o > 0; o >>= 1) p += __shfl_xor_sync(0xffffffffu, p, o);
    const float inv = 1.0f / p;
    const float4 s4 = make_float4(e4.x * inv, e4.y * inv, e4.z * inv, e4.w * inv);

    // ---------------- Phase D: write 16 output rows (STG.128) --------------
    float4* o4 = reinterpret_cast<float4*>(out);
    #pragma unroll
    for (int i = 0; i < 4; ++i) {
        const int rl = i * 4 + q;
        const float v = sh_val[rl];
        o4[(size_t)(blk * 16 + rl) * 256 + col] =
            make_float4(s4.x * v, s4.y * v, s4.z * v, s4.w * v);
    }
}

extern "C" void kernel_launch(void* const* d_in, const int* in_sizes, int n_in,
                              void* d_out, int out_size) {
    // metadata order: queries, keys, values, W, b (queries & bias cancel in softmax)
    const float* keys   = (const float*)d_in[1];
    const float* values = (const float*)d_in[2];
    const float* W      = (const float*)d_in[3];
    float* out = (float*)d_out;

    cudaFuncSetAttribute(k_fused, cudaFuncAttributeMaxDynamicSharedMemorySize,
                         SMEM_BYTES);
    k_fused<<<G_, 1024, SMEM_BYTES>>>(keys, values, W, out);
}

// round 16
// speedup vs baseline: 1.2555x; 1.2226x over previous
#include <cuda_runtime.h>
#include <cstdint>

#define B_  2
#define N_  1024
#define M_  1024
#define H_  128
#define G_  128
#define SCALE_ (1.0f / 6.964404506368992f)  // 1 / 128^0.4

__device__ float g_es[B_ * M_];       // exp(scaled logits)
__device__ float g_psum[G_];          // per-K1-block partial exp sums (64/batch)

// K1 dyn smem layout (bytes):
//   [0,8)           mbar
//   [128, 65664)    W tile (64 KB)
//   [65664, 73856)  part[512] float4 (8 KB)
//   [73856, 74368)  wcol[128]
//   [74368, 74432)  sh_e[16]
#define K1_SMEM 74496

__device__ __forceinline__ uint32_t smem_u32(const void* p) {
    uint32_t a;
    asm("{ .reg .u64 t; cvta.to.shared.u64 t, %1; cvt.u32.u64 %0, t; }"
        : "=r"(a) : "l"(p));
    return a;
}

// ---------------------------------------------------------------------------
// K1: exp(SCALE * keys.colsum(W)) per row + per-block partial sums.
// grid 128 x 512; 16 rows per block (one warp each).
// ---------------------------------------------------------------------------
__global__ __launch_bounds__(512) void k_exps(const float* __restrict__ keys,
                                              const float* __restrict__ W) {
    extern __shared__ char smem[];
    float*  shW  = reinterpret_cast<float*>(smem + 128);
    float4* part = reinterpret_cast<float4*>(smem + 65664);   // 512 float4
    float*  wcol = reinterpret_cast<float*>(smem + 73856);
    float*  sh_e = reinterpret_cast<float*>(smem + 74368);

    const int tid  = threadIdx.x;
    const int lane = tid & 31;
    const int warp = tid >> 5;                 // 0..15
    const int blk  = blockIdx.x;
    const uint32_t mbar = smem_u32(smem);

    // allow dependent kernel to start launching immediately
    cudaTriggerProgrammaticLaunchCompletion();

    if (tid == 0) {
        asm volatile("mbarrier.init.shared.b64 [%0], 1;" :: "r"(mbar) : "memory");
    }
    __syncthreads();
    if (tid == 0) {
        asm volatile("mbarrier.arrive.expect_tx.shared.b64 _, [%0], %1;"
                     :: "r"(mbar), "r"(65536u) : "memory");
        asm volatile(
            "cp.async.bulk.shared::cta.global.mbarrier::complete_tx::bytes "
            "[%0], [%1], %2, [%3];"
            :: "r"(smem_u32(shW)), "l"(W), "r"(65536u), "r"(mbar) : "memory");
    }

    // keys row for this warp -> registers (overlaps with bulk W copy)
    const float4 k4 =
        reinterpret_cast<const float4*>(keys)[(blk * 16 + warp) * 32 + lane];

    // wait for W
    {
        uint32_t done;
        asm volatile(
            "{\n\t.reg .pred p;\n\t"
            "mbarrier.try_wait.parity.acquire.cta.shared::cta.b64 p, [%1], 0;\n\t"
            "selp.b32 %0, 1, 0, p;\n\t}"
            : "=r"(done) : "r"(mbar) : "memory");
        while (!done) {
            asm volatile(
                "{\n\t.reg .pred p;\n\t"
                "mbarrier.try_wait.parity.acquire.cta.shared::cta.b64 p, [%1], 0, 0x989680;\n\t"
                "selp.b32 %0, 1, 0, p;\n\t}"
                : "=r"(done) : "r"(mbar) : "memory");
        }
    }
    __syncthreads();

    // colsum(W): 512 threads, 16 groups x 8 rows
    {
        const int c4 = tid & 31;               // float4 column
        const int g  = tid >> 5;               // 0..15, 8 rows each
        const float4* W4 = reinterpret_cast<const float4*>(shW);
        float4 s = make_float4(0.f, 0.f, 0.f, 0.f);
        #pragma unroll
        for (int r = 0; r < 8; ++r) {
            float4 p = W4[(g * 8 + r) * 32 + c4];
            s.x += p.x; s.y += p.y; s.z += p.z; s.w += p.w;
        }
        part[g * 32 + c4] = s;
    }
    __syncthreads();
    if (tid < 32) {
        float4 s = make_float4(0.f, 0.f, 0.f, 0.f);
        #pragma unroll
        for (int g = 0; g < 16; ++g) {
            float4 p = part[g * 32 + tid];
            s.x += p.x; s.y += p.y; s.z += p.z; s.w += p.w;
        }
        reinterpret_cast<float4*>(wcol)[tid] = s;
    }
    __syncthreads();

    // dot + exp
    {
        const float4 w4 = reinterpret_cast<const float4*>(wcol)[lane];
        float acc = k4.x * w4.x + k4.y * w4.y + k4.z * w4.z + k4.w * w4.w;
        #pragma unroll
        for (int o = 16; o > 0; o >>= 1) acc += __shfl_xor_sync(0xffffffffu, acc, o);
        if (lane == 0) {
            const float e = __expf(SCALE_ * acc);
            __stcg(&g_es[blk * 16 + warp], e);
            sh_e[warp] = e;
        }
    }
    __syncthreads();
    if (warp == 0) {
        float v = (lane < 16) ? sh_e[lane] : 0.f;
        #pragma unroll
        for (int o = 16; o > 0; o >>= 1) v += __shfl_xor_sync(0xffffffffu, v, o);
        if (lane == 0) __stcg(&g_psum[blk], v);  // 0..63 batch0, 64..127 batch1
    }
}

// ---------------------------------------------------------------------------
// K2: denom + scale + output. grid 128 x 1024, PDL-overlapped with K1.
// ---------------------------------------------------------------------------
__global__ __launch_bounds__(1024) void k_out(const float* __restrict__ values,
                                              float* __restrict__ out) {
    __shared__ float sh_val[16];

    const int tid  = threadIdx.x;
    const int lane = tid & 31;
    const int blk  = blockIdx.x;

    // prologue: cold values read, overlapped with K1 execution
    if (tid < 16) sh_val[tid] = values[blk * 16 + tid];
    __syncthreads();

    // wait for K1 grid completion (hardware dependency)
    cudaGridDependencySynchronize();

    const int b   = blk >> 6;
    const int col = tid & 255;
    const int q   = tid >> 8;
    const float4 e4 = __ldcg(
        reinterpret_cast<const float4*>(g_es) + (b << 8) + col);

    float p = __ldcg(&g_psum[b * 64 + lane]) + __ldcg(&g_psum[b * 64 + 32 + lane]);
    #pragma unroll
    for (int o = 16; o > 0; o >>= 1) p += __shfl_xor_sync(0xffffffffu, p, o);
    const float inv = 1.0f / p;
    const float4 s4 = make_float4(e4.x * inv, e4.y * inv, e4.z * inv, e4.w * inv);

    float4* o4 = reinterpret_cast<float4*>(out);
    #pragma unroll
    for (int i = 0; i < 4; ++i) {
        const int rl = i * 4 + q;
        const float v = sh_val[rl];
        o4[(size_t)(blk * 16 + rl) * 256 + col] =
            make_float4(s4.x * v, s4.y * v, s4.z * v, s4.w * v);
    }
}

extern "C" void kernel_launch(void* const* d_in, const int* in_sizes, int n_in,
                              void* d_out, int out_size) {
    // metadata order: queries, keys, values, W, b (queries & bias cancel in softmax)
    const float* keys   = (const float*)d_in[1];
    const float* values = (const float*)d_in[2];
    const float* W      = (const float*)d_in[3];
    float* out = (float*)d_out;

    cudaFuncSetAttribute(k_exps, cudaFuncAttributeMaxDynamicSharedMemorySize,
                         K1_SMEM);

    k_exps<<<G_, 512, K1_SMEM>>>(keys, W);

    // K2 with programmatic dependent launch: overlaps its prologue with K1
    cudaLaunchConfig_t cfg = {};
    cfg.gridDim = dim3(G_, 1, 1);
    cfg.blockDim = dim3(1024, 1, 1);
    cfg.dynamicSmemBytes = 0;
    cudaLaunchAttribute attrs[1];
    attrs[0].id = cudaLaunchAttributeProgrammaticStreamSerialization;
    attrs[0].val.programmaticStreamSerializationAllowed = 1;
    cfg.attrs = attrs;
    cfg.numAttrs = 1;
    cudaLaunchKernelEx(&cfg, k_out, values, out);
}